// round 12
// baseline (speedup 1.0000x reference)
#include <cuda_runtime.h>
#include <stdint.h>

// Problem constants
#define BB     16
#define NCLS   3
#define CREG   50
#define HH     96
#define WW     320
#define HW     (HH*WW)     // 30720
#define KK     100
#define THRESH 0.2f
#define EPSF   1e-6f

// Selection machinery
#define CAP    8192        // per-(b,cls) candidate capacity (expected ~3.4k)
#define CAP2   2048        // survivors after radix-bucket pivot (expected ~150)
#define NBINS  1280        // histogram bins over sigmoid float bits
#define VBASE  0x3E400000u // float bits of 0.1875 (< 0.2); scores in [0.2, 1]
#define BSHIFT 14          // (bits - VBASE) >> 14  -> [0, 1280)

// logit prefilter: any x with sigm_f32(x) >= 0.2 satisfies x > ln(0.25)-1e-4
#define XMIN  (-1.3867f)
// margin below which logit comparison may disagree with rounded-sigmoid
// comparison (f32 sigmoid collision window at realistic logits is <5e-5)
#define COLL_MARGIN 1e-3f

// Global scratch: per-(b,cls) raw candidate keys (keeps dyn smem <= 48KB so
// kernel_launch stays pure kernel launches — no attribute calls in capture)
__device__ unsigned long long g_cand[BB*NCLS][CAP];
// Stage-1 output: per (b,cls) the top-100 as (score_bits<<32)|flat_index
__device__ unsigned long long g_stage1[BB*NCLS*KK];

// Precise sigmoid: expf lowers to libdevice __nv_expf (the most likely match
// for XLA's logistic); __fdiv_rn forces IEEE .rn division even under
// fast-math so score ordering is stable across compile flags.
__device__ __forceinline__ float sigm(float x) {
    return __fdiv_rn(1.0f, 1.0f + expf(-x));
}
__device__ __forceinline__ float reluf(float x) { return x > 0.f ? x : 0.f; }
__device__ __forceinline__ float clampf(float v, float lo, float hi) {
    return fminf(fmaxf(v, lo), hi);
}
__device__ __forceinline__ float max3(float a, float b, float c) {
    return fmaxf(fmaxf(a, b), c);
}

// ---------------------------------------------------------------------------
// Kernel 1: per (b, cls) plane.
//  * 3x3 NMS in LOGIT domain (sigmoid monotone). Marginal band (neighbor max
//    above self by <= COLL_MARGIN) re-checked in rounded-sigmoid space to
//    match the reference's `hmax == heat` comparison exactly.
//  * float4-vectorized: 9x LDG.128 per 4-pixel group, separable 3-tap max.
//  * sigmoid computed only for surviving / marginal pixels (~3k/plane).
//  * warp-aggregated insertion: one atomicAdd per warp ballot, not per lane.
//    (ballot safety: NGROUPS=7680, stride 1024 -> iteration-count boundary at
//    tid=512, a warp boundary, so every warp is convergent at the ballot.)
//  * exact top-100: smem histogram over score bits -> pivot bin -> compact
//    -> bitonic sort of ~150 survivors. Raw candidates staged in gmem scratch.
// grid = 48, block = 1024, dyn smem = keys2(16KB) + hist(5KB) = 21.5KB
// ---------------------------------------------------------------------------
extern __shared__ unsigned char smem_raw[];

__global__ __launch_bounds__(1024)
void nms_topk_kernel(const float* __restrict__ hmp)
{
    unsigned long long* keys2 = (unsigned long long*)smem_raw;            // CAP2
    unsigned int*       hist  = (unsigned int*)(smem_raw + CAP2*8);       // NBINS
    __shared__ int cnt, cnt2, pivot;

    const int tid  = threadIdx.x;
    const int lane = tid & 31;
    const int bc   = blockIdx.x;              // b*NCLS + cls
    const float* base = hmp + (size_t)bc * HW;
    const float4* base4 = (const float4*)base;
    unsigned long long* keys = g_cand[bc];

    if (tid == 0) { cnt = 0; cnt2 = 0; }
    for (int t = tid; t < NBINS; t += 1024) hist[t] = 0u;
    __syncthreads();

    const float4 NEG4 = make_float4(-INFINITY, -INFINITY, -INFINITY, -INFINITY);
    const int NGROUPS = HW/4;                 // 7680, 80 float4-groups per row

    for (int g = tid; g < NGROUPS; g += 1024) {
        int y  = g / (WW/4);
        int xq = g - y*(WW/4);                // group index within row (0..79)
        int rowg = y*(WW/4);

        float4 Cm = __ldg(base4 + rowg + xq);
        // cheap reject: whole group below threshold
        float gmax = fmaxf(fmaxf(Cm.x, Cm.y), fmaxf(Cm.z, Cm.w));

        float m9[4] = {INFINITY, INFINITY, INFINITY, INFINITY};
        if (gmax >= XMIN) {
            float4 Cl = (xq > 0)        ? __ldg(base4 + rowg + xq - 1) : NEG4;
            float4 Cr = (xq < WW/4 - 1) ? __ldg(base4 + rowg + xq + 1) : NEG4;
            float4 Um, Ul, Ur, Dm, Dl, Dr;
            if (y > 0) {
                int rg = rowg - WW/4;
                Um = __ldg(base4 + rg + xq);
                Ul = (xq > 0)        ? __ldg(base4 + rg + xq - 1) : NEG4;
                Ur = (xq < WW/4 - 1) ? __ldg(base4 + rg + xq + 1) : NEG4;
            } else { Um = Ul = Ur = NEG4; }
            if (y < HH-1) {
                int rg = rowg + WW/4;
                Dm = __ldg(base4 + rg + xq);
                Dl = (xq > 0)        ? __ldg(base4 + rg + xq - 1) : NEG4;
                Dr = (xq < WW/4 - 1) ? __ldg(base4 + rg + xq + 1) : NEG4;
            } else { Dm = Dl = Dr = NEG4; }

            // separable 3-tap horizontal max per row (self-inclusive C row)
            float wC0 = max3(Cl.w, Cm.x, Cm.y), wC1 = max3(Cm.x, Cm.y, Cm.z);
            float wC2 = max3(Cm.y, Cm.z, Cm.w), wC3 = max3(Cm.z, Cm.w, Cr.x);
            float wU0 = max3(Ul.w, Um.x, Um.y), wU1 = max3(Um.x, Um.y, Um.z);
            float wU2 = max3(Um.y, Um.z, Um.w), wU3 = max3(Um.z, Um.w, Ur.x);
            float wD0 = max3(Dl.w, Dm.x, Dm.y), wD1 = max3(Dm.x, Dm.y, Dm.z);
            float wD2 = max3(Dm.y, Dm.z, Dm.w), wD3 = max3(Dm.z, Dm.w, Dr.x);

            m9[0] = max3(wU0, wC0, wD0); m9[1] = max3(wU1, wC1, wD1);
            m9[2] = max3(wU2, wC2, wD2); m9[3] = max3(wU3, wC3, wD3);
        }
        float cv[4] = {Cm.x, Cm.y, Cm.z, Cm.w};

        #pragma unroll
        for (int l = 0; l < 4; l++) {
            float v = cv[l];
            bool keep = false;
            float s = 0.f;
            if (gmax >= XMIN && v >= XMIN && m9[l] <= v + COLL_MARGIN) {
                s = sigm(v);
                keep = true;
                if (m9[l] > v) {
                    // marginal band: decide in rounded-sigmoid space, exactly
                    // matching the reference's hmax == heat comparison
                    if (sigm(m9[l]) > s) keep = false;
                }
                if (s < THRESH) keep = false;          // exact threshold
            }
            // warp-aggregated append (order is irrelevant: sorts are total
            // orders over unique keys)
            unsigned ballot = __ballot_sync(0xFFFFFFFFu, keep);
            if (ballot) {
                int nsel = __popc(ballot);
                int leader = __ffs(ballot) - 1;
                int basepos = 0;
                if (lane == leader) basepos = atomicAdd(&cnt, nsel);
                basepos = __shfl_sync(0xFFFFFFFFu, basepos, leader);
                if (keep) {
                    int pos = basepos + __popc(ballot & ((1u << lane) - 1u));
                    if (pos < CAP) {
                        int i = y*WW + xq*4 + l;
                        unsigned vb = __float_as_uint(s);  // bit order = value order
                        keys[pos] = ((unsigned long long)vb << 32) | (unsigned)(~i);
                        unsigned bin = (vb - VBASE) >> BSHIFT;
                        if (bin >= NBINS) bin = NBINS-1;   // s == 1.0 guard
                        atomicAdd(&hist[bin], 1u);
                    }
                }
            }
        }
    }
    __syncthreads();
    int n = cnt; if (n > CAP) n = CAP;

    // pivot: max bin such that count(bins >= pivot) >= K
    // (if fewer than K candidates exist, pivot stays 0 and all survive)
    if (tid == 0) {
        int cum = 0, pb = 0;
        for (int bnum = NBINS-1; bnum >= 0; bnum--) {
            cum += hist[bnum];
            if (cum >= KK) { pb = bnum; break; }
        }
        pivot = pb;
    }
    __syncthreads();
    const int pv = pivot;

    // compact survivors (all top-K guaranteed in bins >= pivot;
    // survivor count <= (K-1) + hist[pivot] << CAP2 for this data)
    for (int t = tid; t < n; t += 1024) {
        unsigned long long e = keys[t];
        unsigned vb = (unsigned)(e >> 32);
        unsigned bin = (vb - VBASE) >> BSHIFT;
        if (bin >= NBINS) bin = NBINS-1;
        if ((int)bin >= pv) {
            int pos = atomicAdd(&cnt2, 1);
            if (pos < CAP2) keys2[pos] = e;
        }
    }
    __syncthreads();
    int m = cnt2; if (m > CAP2) m = CAP2;
    int N2 = 128; while (N2 < m) N2 <<= 1;        // pad to pow2 (>=128 > K)
    for (int t = tid; t < N2; t += 1024) if (t >= m) keys2[t] = 0ull;
    __syncthreads();

    // bitonic sort descending over N2 (typically 256); all keys distinct
    // (unique index in low bits) -> deterministic result regardless of
    // atomic fill order
    for (int k2 = 2; k2 <= N2; k2 <<= 1) {
        for (int j = k2 >> 1; j > 0; j >>= 1) {
            for (int t = tid; t < N2; t += 1024) {
                int ixj = t ^ j;
                if (ixj > t) {
                    unsigned long long a = keys2[t], b = keys2[ixj];
                    bool desc = ((t & k2) == 0);
                    if (desc ? (a < b) : (a > b)) { keys2[t] = b; keys2[ixj] = a; }
                }
            }
            __syncthreads();
        }
    }

    if (tid < KK) {
        unsigned long long e = keys2[tid];
        unsigned vb  = (unsigned)(e >> 32);
        unsigned idx = ~(unsigned)e;              // zero-pad -> score 0, masked later
        g_stage1[bc*KK + tid] = ((unsigned long long)vb << 32) | idx;
    }
}

// ---------------------------------------------------------------------------
// Kernel 2: per image — merge 3x100 into global top-100 (value desc, position
// asc == reference's second top_k over the 300-array; supra-threshold entries
// form a prefix of each per-class sorted list so positions match), then gather
// 34 reg channels per detection and run the MonoFlex geometric decode.
// grid = 16, block = 256
// ---------------------------------------------------------------------------
__global__ __launch_bounds__(256)
void decode_kernel(const float* __restrict__ reg,
                   const float* __restrict__ calib,
                   const float* __restrict__ pad_size,
                   const float* __restrict__ dim_mean,
                   float* __restrict__ out)
{
    __shared__ unsigned long long kk[512];
    const int tid = threadIdx.x;
    const int b   = blockIdx.x;

    for (int t = tid; t < 512; t += 256) {
        unsigned long long key = 0ull;
        if (t < NCLS*KK) {
            unsigned long long e = g_stage1[b*NCLS*KK + t];   // pos t = cls*100+rank
            key = (e & 0xFFFFFFFF00000000ull) | (unsigned)(~t);
        }
        kk[t] = key;
    }
    __syncthreads();

    for (int k2 = 2; k2 <= 512; k2 <<= 1) {
        for (int j = k2 >> 1; j > 0; j >>= 1) {
            for (int t = tid; t < 512; t += 256) {
                int ixj = t ^ j;
                if (ixj > t) {
                    unsigned long long a = kk[t], bv = kk[ixj];
                    bool desc = ((t & k2) == 0);
                    if (desc ? (a < bv) : (a > bv)) { kk[t] = bv; kk[ixj] = a; }
                }
            }
            __syncthreads();
        }
    }

    if (tid < KK) {
        unsigned long long e = kk[tid];
        float score = __uint_as_float((unsigned)(e >> 32));
        float* row = out + (size_t)(b*KK + tid) * 13;
        if (!(score >= THRESH)) {
            #pragma unroll
            for (int c = 0; c < 13; c++) row[c] = 0.f;   // mask == 0 -> zero row
        } else {
            int pos = (int)(~(unsigned)e) & 0x1FF;       // position in 300-array
            int cls = pos / KK;
            unsigned idx = (unsigned)(g_stage1[b*NCLS*KK + pos] & 0xFFFFFFFFull);
            const float* rb = reg + (size_t)b*CREG*HW + idx;

            float pc[9];                                  // channels 0..8
            #pragma unroll
            for (int c = 0; c < 9; c++)  pc[c] = __ldg(rb + (size_t)c*HW);
            float pk[25];                                 // channels 25..49
            #pragma unroll
            for (int c = 0; c < 25; c++) pk[c] = __ldg(rb + (size_t)(25+c)*HW);

            float xs = (float)(idx % WW);
            float ys = (float)(idx / WW);
            float fu = __ldg(calib + b*4 + 0), cu = __ldg(calib + b*4 + 1);
            float fv = __ldg(calib + b*4 + 2), cv = __ldg(calib + b*4 + 3);
            float pd0 = __ldg(pad_size + b*2 + 0), pd1 = __ldg(pad_size + b*2 + 1);

            float d0 = expf(pc[6]) * __ldg(dim_mean + cls*3 + 0);
            float d1 = expf(pc[7]) * __ldg(dim_mean + cls*3 + 1);
            float d2 = expf(pc[8]) * __ldg(dim_mean + cls*3 + 2);
            float h3d = d1;

            float sg = sigm(pk[23]);                            // doff = pois[48]
            float dd = clampf(__fdiv_rn(1.0f, sg) - 1.0f, 0.1f, 100.0f);

            float fuh = fu * h3d;
            // kpt[j].y = pois[25+2j+1] = pk[2j+1]
            float dctr = clampf(fuh/(reluf(pk[17]-pk[19])*4.0f + EPSF), 0.1f, 100.0f);
            float a02 = fuh/(reluf(pk[1]-pk[9])*4.0f + EPSF);
            float b02 = fuh/(reluf(pk[5]-pk[13])*4.0f + EPSF);
            float d02 = clampf((a02 + b02)*0.5f, 0.1f, 100.0f);
            float a13 = fuh/(reluf(pk[3]-pk[11])*4.0f + EPSF);
            float b13 = fuh/(reluf(pk[7]-pk[15])*4.0f + EPSF);
            float d13 = clampf((a13 + b13)*0.5f, 0.1f, 100.0f);

            float u0 = expf(pk[24]);                             // dunc
            float u1 = expf(pk[20]), u2 = expf(pk[21]), u3 = expf(pk[22]); // cunc
            float w0 = 1.0f/u0, w1 = 1.0f/u1, w2 = 1.0f/u2, w3 = 1.0f/u3;
            float S  = w0 + w1 + w2 + w3;
            float wn0 = w0/S, wn1 = w1/S, wn2 = w2/S, wn3 = w3/S;
            float depth = dd*wn0 + dctr*wn1 + d02*wn2 + d13*wn3;
            float derr  = wn0*u0 + wn1*u1 + wn2*u2 + wn3*u3;

            float bx0 = clampf((xs - reluf(pc[0]))*4.0f - pd0, 0.0f, 1279.0f);
            float by0 = clampf((ys - reluf(pc[1]))*4.0f - pd1, 0.0f, 383.0f);
            float bx1 = clampf((xs + reluf(pc[2]))*4.0f - pd0, 0.0f, 1279.0f);
            float by1 = clampf((ys + reluf(pc[3]))*4.0f - pd1, 0.0f, 383.0f);

            float px = (xs + pc[4])*4.0f - pd0;
            float py = (ys + pc[5])*4.0f - pd1;
            float x3 = (px - cu)*depth/fu;
            float y3 = (py - cv)*depth/fv;

            row[0]  = (float)cls; row[1]  = score;
            row[2]  = bx0;        row[3]  = by0;
            row[4]  = bx1;        row[5]  = by1;
            row[6]  = d0;         row[7]  = d1;   row[8] = d2;
            row[9]  = x3;         row[10] = y3;   row[11] = depth;
            row[12] = derr;
        }
    }
}

extern "C" void kernel_launch(void* const* d_in, const int* in_sizes, int n_in,
                              void* d_out, int out_size)
{
    const float* hmp   = (const float*)d_in[0];
    const float* reg   = (const float*)d_in[1];
    const float* calib = (const float*)d_in[2];
    const float* pads  = (const float*)d_in[3];
    const float* dimm  = (const float*)d_in[4];
    float* out = (float*)d_out;

    const int shbytes = CAP2*8 + NBINS*4;     // 16384 + 5120 = 21504 (<48KB, no opt-in)
    nms_topk_kernel<<<BB*NCLS, 1024, shbytes>>>(hmp);
    decode_kernel<<<BB, 256>>>(reg, calib, pads, dimm, out);
}

// round 13
// speedup vs baseline: 1.0677x; 1.0677x over previous
#include <cuda_runtime.h>
#include <stdint.h>

// Problem constants
#define BB     16
#define NCLS   3
#define CREG   50
#define HH     96
#define WW     320
#define HW     (HH*WW)     // 30720
#define KK     100
#define THRESH 0.2f
#define EPSF   1e-6f

// Selection machinery
#define CAP    8192
#define CAP2   2048
#define NBINS  1280
#define VBASE  0x3E400000u
#define BSHIFT 14

#define XMIN  (-1.3867f)
#define COLL_MARGIN 1e-3f

__device__ unsigned long long g_cand[BB*NCLS][CAP];
__device__ unsigned long long g_stage1[BB*NCLS*KK];

__device__ __forceinline__ float sigm(float x) {
    return __fdiv_rn(1.0f, 1.0f + expf(-x));
}
__device__ __forceinline__ float reluf(float x) { return x > 0.f ? x : 0.f; }
__device__ __forceinline__ float clampf(float v, float lo, float hi) {
    return fminf(fmaxf(v, lo), hi);
}
__device__ __forceinline__ float max3(float a, float b, float c) {
    return fmaxf(fmaxf(a, b), c);
}

// ---------------------------------------------------------------------------
// Kernel 1: UNCHANGED from the passing R12 baseline (single-variable change).
// ---------------------------------------------------------------------------
extern __shared__ unsigned char smem_raw[];

__global__ __launch_bounds__(1024)
void nms_topk_kernel(const float* __restrict__ hmp)
{
    unsigned long long* keys2 = (unsigned long long*)smem_raw;            // CAP2
    unsigned int*       hist  = (unsigned int*)(smem_raw + CAP2*8);       // NBINS
    __shared__ int cnt, cnt2, pivot;

    const int tid  = threadIdx.x;
    const int lane = tid & 31;
    const int bc   = blockIdx.x;
    const float* base = hmp + (size_t)bc * HW;
    const float4* base4 = (const float4*)base;
    unsigned long long* keys = g_cand[bc];

    if (tid == 0) { cnt = 0; cnt2 = 0; }
    for (int t = tid; t < NBINS; t += 1024) hist[t] = 0u;
    __syncthreads();

    const float4 NEG4 = make_float4(-INFINITY, -INFINITY, -INFINITY, -INFINITY);
    const int NGROUPS = HW/4;

    for (int g = tid; g < NGROUPS; g += 1024) {
        int y  = g / (WW/4);
        int xq = g - y*(WW/4);
        int rowg = y*(WW/4);

        float4 Cm = __ldg(base4 + rowg + xq);
        float gmax = fmaxf(fmaxf(Cm.x, Cm.y), fmaxf(Cm.z, Cm.w));

        float m9[4] = {INFINITY, INFINITY, INFINITY, INFINITY};
        if (gmax >= XMIN) {
            float4 Cl = (xq > 0)        ? __ldg(base4 + rowg + xq - 1) : NEG4;
            float4 Cr = (xq < WW/4 - 1) ? __ldg(base4 + rowg + xq + 1) : NEG4;
            float4 Um, Ul, Ur, Dm, Dl, Dr;
            if (y > 0) {
                int rg = rowg - WW/4;
                Um = __ldg(base4 + rg + xq);
                Ul = (xq > 0)        ? __ldg(base4 + rg + xq - 1) : NEG4;
                Ur = (xq < WW/4 - 1) ? __ldg(base4 + rg + xq + 1) : NEG4;
            } else { Um = Ul = Ur = NEG4; }
            if (y < HH-1) {
                int rg = rowg + WW/4;
                Dm = __ldg(base4 + rg + xq);
                Dl = (xq > 0)        ? __ldg(base4 + rg + xq - 1) : NEG4;
                Dr = (xq < WW/4 - 1) ? __ldg(base4 + rg + xq + 1) : NEG4;
            } else { Dm = Dl = Dr = NEG4; }

            float wC0 = max3(Cl.w, Cm.x, Cm.y), wC1 = max3(Cm.x, Cm.y, Cm.z);
            float wC2 = max3(Cm.y, Cm.z, Cm.w), wC3 = max3(Cm.z, Cm.w, Cr.x);
            float wU0 = max3(Ul.w, Um.x, Um.y), wU1 = max3(Um.x, Um.y, Um.z);
            float wU2 = max3(Um.y, Um.z, Um.w), wU3 = max3(Um.z, Um.w, Ur.x);
            float wD0 = max3(Dl.w, Dm.x, Dm.y), wD1 = max3(Dm.x, Dm.y, Dm.z);
            float wD2 = max3(Dm.y, Dm.z, Dm.w), wD3 = max3(Dm.z, Dm.w, Dr.x);

            m9[0] = max3(wU0, wC0, wD0); m9[1] = max3(wU1, wC1, wD1);
            m9[2] = max3(wU2, wC2, wD2); m9[3] = max3(wU3, wC3, wD3);
        }
        float cv[4] = {Cm.x, Cm.y, Cm.z, Cm.w};

        #pragma unroll
        for (int l = 0; l < 4; l++) {
            float v = cv[l];
            bool keep = false;
            float s = 0.f;
            if (gmax >= XMIN && v >= XMIN && m9[l] <= v + COLL_MARGIN) {
                s = sigm(v);
                keep = true;
                if (m9[l] > v) {
                    if (sigm(m9[l]) > s) keep = false;
                }
                if (s < THRESH) keep = false;
            }
            unsigned ballot = __ballot_sync(0xFFFFFFFFu, keep);
            if (ballot) {
                int nsel = __popc(ballot);
                int leader = __ffs(ballot) - 1;
                int basepos = 0;
                if (lane == leader) basepos = atomicAdd(&cnt, nsel);
                basepos = __shfl_sync(0xFFFFFFFFu, basepos, leader);
                if (keep) {
                    int pos = basepos + __popc(ballot & ((1u << lane) - 1u));
                    if (pos < CAP) {
                        int i = y*WW + xq*4 + l;
                        unsigned vb = __float_as_uint(s);
                        keys[pos] = ((unsigned long long)vb << 32) | (unsigned)(~i);
                        unsigned bin = (vb - VBASE) >> BSHIFT;
                        if (bin >= NBINS) bin = NBINS-1;
                        atomicAdd(&hist[bin], 1u);
                    }
                }
            }
        }
    }
    __syncthreads();
    int n = cnt; if (n > CAP) n = CAP;

    if (tid == 0) {
        int cum = 0, pb = 0;
        for (int bnum = NBINS-1; bnum >= 0; bnum--) {
            cum += hist[bnum];
            if (cum >= KK) { pb = bnum; break; }
        }
        pivot = pb;
    }
    __syncthreads();
    const int pv = pivot;

    for (int t = tid; t < n; t += 1024) {
        unsigned long long e = keys[t];
        unsigned vb = (unsigned)(e >> 32);
        unsigned bin = (vb - VBASE) >> BSHIFT;
        if (bin >= NBINS) bin = NBINS-1;
        if ((int)bin >= pv) {
            int pos = atomicAdd(&cnt2, 1);
            if (pos < CAP2) keys2[pos] = e;
        }
    }
    __syncthreads();
    int m = cnt2; if (m > CAP2) m = CAP2;
    int N2 = 128; while (N2 < m) N2 <<= 1;
    for (int t = tid; t < N2; t += 1024) if (t >= m) keys2[t] = 0ull;
    __syncthreads();

    for (int k2 = 2; k2 <= N2; k2 <<= 1) {
        for (int j = k2 >> 1; j > 0; j >>= 1) {
            for (int t = tid; t < N2; t += 1024) {
                int ixj = t ^ j;
                if (ixj > t) {
                    unsigned long long a = keys2[t], b = keys2[ixj];
                    bool desc = ((t & k2) == 0);
                    if (desc ? (a < b) : (a > b)) { keys2[t] = b; keys2[ixj] = a; }
                }
            }
            __syncthreads();
        }
    }

    if (tid < KK) {
        unsigned long long e = keys2[tid];
        unsigned vb  = (unsigned)(e >> 32);
        unsigned idx = ~(unsigned)e;
        g_stage1[bc*KK + tid] = ((unsigned long long)vb << 32) | idx;
    }
}

// ---------------------------------------------------------------------------
// Kernel 2 (REWRITTEN): per image.
//  * 3-way MERGE instead of 512-bitonic: per-class lists are sorted desc by
//    composite key (score_bits<<32)|~pos, so each entry's global rank =
//    rank-in-own-list + binary-search counts in the other two lists. Same
//    total order as the old sort (identical keys), zero barrier stages.
//  * Cooperative gather: all 256 threads service the 100x34 channel loads
//    into padded smem -> ~14 independent loads in flight per thread.
//  * Threads 0..99 run the (unchanged) MonoFlex decode math from smem.
// grid = 16, block = 256, static smem ~ 18.5KB
// ---------------------------------------------------------------------------
#define NCH 34            // 9 (ch 0..8) + 25 (ch 25..49)
#define NPK_OFF 9         // pois[] split point

__global__ __launch_bounds__(256)
void decode_kernel(const float* __restrict__ reg,
                   const float* __restrict__ calib,
                   const float* __restrict__ pad_size,
                   const float* __restrict__ dim_mean,
                   float* __restrict__ out)
{
    __shared__ unsigned long long skeys[NCLS*KK];   // 300 composite keys
    __shared__ int   r2pos[KK];                     // rank -> pos in 300-array
    __shared__ int   r2idx[KK];                     // rank -> flat index (-1 = masked)
    __shared__ float r2score[KK];
    __shared__ int   r2cls[KK];
    __shared__ float pois[KK][NCH+1];               // +1 pad: bank-conflict-free rows

    const int tid = threadIdx.x;
    const int b   = blockIdx.x;

    // load composite keys (same keys the old bitonic sorted)
    for (int t = tid; t < NCLS*KK; t += 256) {
        unsigned long long e = g_stage1[b*NCLS*KK + t];
        skeys[t] = (e & 0xFFFFFFFF00000000ull) | (unsigned)(~t);
    }
    __syncthreads();

    // rank via 3-way merge: keys within each class list are strictly
    // decreasing, and all 300 keys are globally unique (distinct ~t).
    if (tid < NCLS*KK) {
        unsigned long long k = skeys[tid];
        int myclass = tid / KK;
        int rank = tid - myclass*KK;               // greater-count in own list
        #pragma unroll
        for (int o = 0; o < NCLS; o++) {
            if (o == myclass) continue;
            int basei = o*KK;
            int lo = 0, hi = KK;
            while (lo < hi) {                      // count keys > k in list o
                int mid = (lo + hi) >> 1;
                if (skeys[basei + mid] > k) lo = mid + 1; else hi = mid;
            }
            rank += lo;
        }
        if (rank < KK) r2pos[rank] = tid;
    }
    __syncthreads();

    // per-detection metadata
    if (tid < KK) {
        int pos = r2pos[tid];
        unsigned long long e = g_stage1[b*NCLS*KK + pos];
        float score = __uint_as_float((unsigned)(e >> 32));
        r2score[tid] = score;
        r2cls[tid]   = pos / KK;
        r2idx[tid]   = (score >= THRESH) ? (int)(e & 0xFFFFFFFFull) : -1;
    }
    __syncthreads();

    // cooperative gather: 100 x 34 channel loads spread over all 256 threads
    const float* regb = reg + (size_t)b*CREG*HW;
    for (int u = tid; u < KK*NCH; u += 256) {
        int d = u / NCH;
        int c = u - d*NCH;
        int idx = r2idx[d];
        if (idx >= 0) {
            int chan = (c < NPK_OFF) ? c : (c + 16);   // 9..33 -> 25..49
            pois[d][c] = __ldg(regb + (size_t)chan*HW + idx);
        }
    }
    __syncthreads();

    // decode (threads 0..99) — math identical to the passing baseline
    if (tid < KK) {
        float score = r2score[tid];
        float* row = out + (size_t)(b*KK + tid) * 13;
        int idx = r2idx[tid];
        if (idx < 0) {
            #pragma unroll
            for (int c = 0; c < 13; c++) row[c] = 0.f;
        } else {
            int cls = r2cls[tid];
            const float* pc = &pois[tid][0];        // channels 0..8
            const float* pk = &pois[tid][NPK_OFF];  // channels 25..49

            float xs = (float)(idx % WW);
            float ys = (float)(idx / WW);
            float fu = __ldg(calib + b*4 + 0), cu = __ldg(calib + b*4 + 1);
            float fv = __ldg(calib + b*4 + 2), cv = __ldg(calib + b*4 + 3);
            float pd0 = __ldg(pad_size + b*2 + 0), pd1 = __ldg(pad_size + b*2 + 1);

            float d0 = expf(pc[6]) * __ldg(dim_mean + cls*3 + 0);
            float d1 = expf(pc[7]) * __ldg(dim_mean + cls*3 + 1);
            float d2 = expf(pc[8]) * __ldg(dim_mean + cls*3 + 2);
            float h3d = d1;

            float sg = sigm(pk[23]);
            float dd = clampf(__fdiv_rn(1.0f, sg) - 1.0f, 0.1f, 100.0f);

            float fuh = fu * h3d;
            float dctr = clampf(fuh/(reluf(pk[17]-pk[19])*4.0f + EPSF), 0.1f, 100.0f);
            float a02 = fuh/(reluf(pk[1]-pk[9])*4.0f + EPSF);
            float b02 = fuh/(reluf(pk[5]-pk[13])*4.0f + EPSF);
            float d02 = clampf((a02 + b02)*0.5f, 0.1f, 100.0f);
            float a13 = fuh/(reluf(pk[3]-pk[11])*4.0f + EPSF);
            float b13 = fuh/(reluf(pk[7]-pk[15])*4.0f + EPSF);
            float d13 = clampf((a13 + b13)*0.5f, 0.1f, 100.0f);

            float u0 = expf(pk[24]);
            float u1 = expf(pk[20]), u2 = expf(pk[21]), u3 = expf(pk[22]);
            float w0 = 1.0f/u0, w1 = 1.0f/u1, w2 = 1.0f/u2, w3 = 1.0f/u3;
            float S  = w0 + w1 + w2 + w3;
            float wn0 = w0/S, wn1 = w1/S, wn2 = w2/S, wn3 = w3/S;
            float depth = dd*wn0 + dctr*wn1 + d02*wn2 + d13*wn3;
            float derr  = wn0*u0 + wn1*u1 + wn2*u2 + wn3*u3;

            float bx0 = clampf((xs - reluf(pc[0]))*4.0f - pd0, 0.0f, 1279.0f);
            float by0 = clampf((ys - reluf(pc[1]))*4.0f - pd1, 0.0f, 383.0f);
            float bx1 = clampf((xs + reluf(pc[2]))*4.0f - pd0, 0.0f, 1279.0f);
            float by1 = clampf((ys + reluf(pc[3]))*4.0f - pd1, 0.0f, 383.0f);

            float px = (xs + pc[4])*4.0f - pd0;
            float py = (ys + pc[5])*4.0f - pd1;
            float x3 = (px - cu)*depth/fu;
            float y3 = (py - cv)*depth/fv;

            row[0]  = (float)cls; row[1]  = score;
            row[2]  = bx0;        row[3]  = by0;
            row[4]  = bx1;        row[5]  = by1;
            row[6]  = d0;         row[7]  = d1;   row[8] = d2;
            row[9]  = x3;         row[10] = y3;   row[11] = depth;
            row[12] = derr;
        }
    }
}

extern "C" void kernel_launch(void* const* d_in, const int* in_sizes, int n_in,
                              void* d_out, int out_size)
{
    const float* hmp   = (const float*)d_in[0];
    const float* reg   = (const float*)d_in[1];
    const float* calib = (const float*)d_in[2];
    const float* pads  = (const float*)d_in[3];
    const float* dimm  = (const float*)d_in[4];
    float* out = (float*)d_out;

    const int shbytes = CAP2*8 + NBINS*4;     // 21504 (<48KB, no opt-in)
    nms_topk_kernel<<<BB*NCLS, 1024, shbytes>>>(hmp);
    decode_kernel<<<BB, 256>>>(reg, calib, pads, dimm, out);
}